// round 11
// baseline (speedup 1.0000x reference)
#include <cuda_runtime.h>
#include <cstdint>

// LIF neuron scan: v = 0.5*v + x_t; spike = (v >= 1); v = spike ? 0 : v
// x: [T, B, D] f32, v0: [D] f32, out spikes: [T, B, D] f32.
//
// R11: reads = proven per-thread cp.async SMEM ring (24 stages, 3 groups of
// 8, positional wait_group). Writes = NEW: spikes staged in SMEM (double
// buffer) and drained with cp.async.bulk.global.shared::cta (UBLKCP) — one
// 1776B contiguous bulk write per timestep row per CTA, issued by a single
// thread, instead of warp-interleaved STG.64. Tests whether long
// same-direction write bursts raise mixed r/w DRAM efficiency past the
// ~5.67 TB/s wall every STG variant has hit.

#define LIF_CTA     256
#define LIF_GRID    148
#define LIF_CHUNK   222                    // chains per CTA (148*222 >= 32768)
#define LIF_RB      8                      // timesteps per batch
#define LIF_RGROUPS 3
#define LIF_RSTAGES (LIF_RB * LIF_RGROUPS) // 24
#define LIF_TAU     0.5f

#define RING_BYTES  (LIF_RSTAGES * LIF_CHUNK * 8)        // 42624
#define STAG_BYTES  (2 * LIF_RB * LIF_CHUNK * 8)         // 28416
#define LIF_SMEM    (RING_BYTES + STAG_BYTES)            // 71040

__global__ void __launch_bounds__(LIF_CTA, 1)
lif_scan_kernel(const float* __restrict__ x,
                const float* __restrict__ v0,
                float* __restrict__ out,
                int T, int N2, int D2)
{
    extern __shared__ char smem[];
    float2* stag = (float2*)(smem + RING_BYTES);   // [2][LIF_RB][LIF_CHUNK]

    const int base = blockIdx.x * LIF_CHUNK;
    const int nloc = min(LIF_CHUNK, N2 - base);    // chains in this CTA
    if (nloc <= 0) return;                          // whole CTA exits together

    const int  tid    = threadIdx.x;
    const bool active = tid < nloc;
    const int  chain  = base + tid;

    uint32_t ring0 = (uint32_t)__cvta_generic_to_shared(smem) + (uint32_t)tid * 8u;
    uint32_t stag0 = (uint32_t)__cvta_generic_to_shared(stag);
    const uint32_t stage_bytes = LIF_CHUNK * 8u;

    const char* gp = (const char*)x + (size_t)chain * 8u;
    const size_t gstride = (size_t)N2 * 8u;        // bytes per timestep

    uint64_t pol_r;
    asm volatile("createpolicy.fractional.L2::evict_first.b64 %0, 1.0;\n"
                 : "=l"(pol_r));

    // ---- prologue: fill RGROUPS-1 = 2 groups (16 stages) ----
    #pragma unroll
    for (int g = 0; g < LIF_RGROUPS - 1; g++) {
        if (active) {
            #pragma unroll
            for (int j = 0; j < LIF_RB; j++) {
                uint32_t dst = ring0 + (uint32_t)(g * LIF_RB + j) * stage_bytes;
                asm volatile(
                    "cp.async.ca.shared.global.L2::cache_hint [%0], [%1], 8, %2;\n"
                    :: "r"(dst), "l"(gp), "l"(pol_r) : "memory");
                gp += gstride;
            }
        }
        asm volatile("cp.async.commit_group;\n" ::: "memory");
    }

    // initial membrane potential
    float2 v = make_float2(0.f, 0.f);
    if (active) v = ((const float2*)v0)[chain % D2];

    int wgrp = LIF_RGROUPS - 1;
    int rslot = 0;
    int buf = 0;
    const int prefetched = (LIF_RGROUPS - 1) * LIF_RB;   // 16

    for (int t = 0; t < T; t += LIF_RB) {
        // ---- read burst for steps t+16..t+23 ----
        if (t + prefetched < T && active) {
            #pragma unroll
            for (int j = 0; j < LIF_RB; j++) {
                uint32_t dst = ring0 +
                    (uint32_t)(wgrp * LIF_RB + j) * stage_bytes;
                asm volatile(
                    "cp.async.ca.shared.global.L2::cache_hint [%0], [%1], 8, %2;\n"
                    :: "r"(dst), "l"(gp), "l"(pol_r) : "memory");
                gp += gstride;
            }
        }
        asm volatile("cp.async.commit_group;\n" ::: "memory");
        if (++wgrp == LIF_RGROUPS) wgrp = 0;

        asm volatile("cp.async.wait_group %0;\n" :: "n"(LIF_RGROUPS - 1) : "memory");

        // staging[buf]'s previous bulk-store group must have drained before
        // we overwrite it (2 groups ago -> wait <=1 outstanding)
        if (tid == 0)
            asm volatile("cp.async.bulk.wait_group %0;\n" :: "n"(1) : "memory");
        __syncthreads();

        // ---- compute 8 steps into staging[buf] ----
        #pragma unroll
        for (int j = 0; j < LIF_RB; j++) {
            if (active) {
                float2 xt;
                uint32_t src = ring0 + (uint32_t)rslot * stage_bytes;
                asm volatile("ld.shared.v2.f32 {%0,%1}, [%2];\n"
                             : "=f"(xt.x), "=f"(xt.y) : "r"(src));

                float2 sp;
                v.x = fmaf(LIF_TAU, v.x, xt.x);
                v.y = fmaf(LIF_TAU, v.y, xt.y);
                bool fx = v.x >= 1.0f, fy = v.y >= 1.0f;
                sp.x = fx ? 1.0f : 0.0f;  v.x = fx ? 0.0f : v.x;
                sp.y = fy ? 1.0f : 0.0f;  v.y = fy ? 0.0f : v.y;

                stag[(buf * LIF_RB + j) * LIF_CHUNK + tid] = sp;
            }
            if (++rslot == LIF_RSTAGES) rslot = 0;
        }
        __syncthreads();   // staging writes visible CTA-wide

        // ---- bulk-store 8 rows (1 thread, async proxy) ----
        if (tid == 0) {
            asm volatile("fence.proxy.async;\n" ::: "memory");
            const char* ob = (const char*)out +
                             (size_t)t * gstride + (size_t)base * 8u;
            uint32_t ss = stag0 + (uint32_t)(buf * LIF_RB * LIF_CHUNK * 8);
            const uint32_t sz = (uint32_t)nloc * 8u;   // multiple of 16
            #pragma unroll
            for (int j = 0; j < LIF_RB; j++) {
                asm volatile(
                    "cp.async.bulk.global.shared::cta.bulk_group [%0], [%1], %2;\n"
                    :: "l"(ob), "r"(ss), "r"(sz) : "memory");
                ob += gstride;
                ss += LIF_CHUNK * 8u;
            }
            asm volatile("cp.async.bulk.commit_group;\n" ::: "memory");
        }
        buf ^= 1;
    }

    // drain outstanding bulk stores before exit
    if (tid == 0)
        asm volatile("cp.async.bulk.wait_group %0;\n" :: "n"(0) : "memory");
}

extern "C" void kernel_launch(void* const* d_in, const int* in_sizes, int n_in,
                              void* d_out, int out_size)
{
    const float* x  = (const float*)d_in[0];   // [T, B, D]
    const float* v0 = (const float*)d_in[1];   // [D]
    float* out = (float*)d_out;

    const int T = 512;                 // fixed by problem setup
    const int total = in_sizes[0];     // T*B*D
    const int D = in_sizes[1];
    const int N  = total / T;          // B*D
    const int N2 = N / 2;              // float2 chains
    const int D2 = D / 2;

    static bool attr_done = false;
    if (!attr_done) {
        cudaFuncSetAttribute(lif_scan_kernel,
                             cudaFuncAttributeMaxDynamicSharedMemorySize,
                             LIF_SMEM);
        attr_done = true;
    }

    int grid = (N2 + LIF_CHUNK - 1) / LIF_CHUNK;   // 148 for N2=32768
    lif_scan_kernel<<<grid, LIF_CTA, LIF_SMEM>>>(x, v0, out, T, N2, D2);
}

// round 12
// speedup vs baseline: 1.7002x; 1.7002x over previous
#include <cuda_runtime.h>
#include <cstdint>

// LIF neuron scan: v = 0.5*v + x_t; spike = (v >= 1); v = spike ? 0 : v
// x: [T, B, D] f32, v0: [D] f32, out spikes: [T, B, D] f32.
//
// Final form (R8 structure): float2 chains, per-thread 24-stage cp.async SMEM
// ring (6 groups of 4), positional wait_group ordering, no __syncthreads.
// Reads L2::evict_first, stores __stcs.
// R12 hygiene: 128 CTAs x 256 threads = exactly 32768 chains -> every thread
// active, all warps full, no guard divergence.
//
// Measured model: harness steady state is pinned at ~5.67 TB/s mixed R/W
// DRAM bandwidth; with 268 MB irreducible traffic this kernel sits on that
// roofline (occupancy/slack/hint/burst levers all proven neutral in R1-R11).

#define LIF_CTA    256
#define LIF_BATCH  4
#define LIF_GROUPS 6
#define LIF_STAGES (LIF_BATCH * LIF_GROUPS)   // 24 slots x 256 thr x 8B = 48 KB
#define LIF_TAU    0.5f

__global__ void __launch_bounds__(LIF_CTA, 1)
lif_scan_kernel(const float* __restrict__ x,
                const float* __restrict__ v0,
                float* __restrict__ out,
                int T, int N2, int D2)
{
    __shared__ float2 ring[LIF_STAGES][LIF_CTA];

    const int chain = blockIdx.x * LIF_CTA + threadIdx.x;
    if (chain >= N2) return;

    uint32_t slot0 = (uint32_t)__cvta_generic_to_shared(&ring[0][threadIdx.x]);
    const uint32_t stage_bytes = LIF_CTA * 8u;

    const char* gp = (const char*)x + (size_t)chain * 8u;
    const size_t gstride = (size_t)N2 * 8u;      // bytes per timestep

    // L2 evict-first for the read-once input stream
    uint64_t pol_r;
    asm volatile("createpolicy.fractional.L2::evict_first.b64 %0, 1.0;\n"
                 : "=l"(pol_r));

    // ---- prologue: fill GROUPS-1 = 5 groups (20 stages) ----
    #pragma unroll
    for (int g = 0; g < LIF_GROUPS - 1; g++) {
        #pragma unroll
        for (int j = 0; j < LIF_BATCH; j++) {
            uint32_t dst = slot0 + (uint32_t)(g * LIF_BATCH + j) * stage_bytes;
            asm volatile(
                "cp.async.ca.shared.global.L2::cache_hint [%0], [%1], 8, %2;\n"
                :: "r"(dst), "l"(gp), "l"(pol_r) : "memory");
            gp += gstride;
        }
        asm volatile("cp.async.commit_group;\n" ::: "memory");
    }

    // initial membrane potential: v0[d] broadcast over batch
    float2 v = ((const float2*)v0)[chain % D2];

    float2* op = (float2*)out + chain;

    int wgrp = LIF_GROUPS - 1;   // ring group to write next
    int rslot = 0;               // stage slot to read next

    const int prefetched = (LIF_GROUPS - 1) * LIF_BATCH;   // 20 steps

    for (int t = 0; t < T; t += LIF_BATCH) {
        // issue group for steps t+20..t+23 (if any); ALWAYS commit one group
        // per iteration so positional wait_group accounting holds
        if (t + prefetched < T) {
            #pragma unroll
            for (int j = 0; j < LIF_BATCH; j++) {
                uint32_t dst = slot0 +
                    (uint32_t)(wgrp * LIF_BATCH + j) * stage_bytes;
                asm volatile(
                    "cp.async.ca.shared.global.L2::cache_hint [%0], [%1], 8, %2;\n"
                    :: "r"(dst), "l"(gp), "l"(pol_r) : "memory");
                gp += gstride;
            }
        }
        asm volatile("cp.async.commit_group;\n" ::: "memory");
        if (++wgrp == LIF_GROUPS) wgrp = 0;

        // all but the 5 most recent groups complete -> this batch landed
        asm volatile("cp.async.wait_group %0;\n" :: "n"(LIF_GROUPS - 1) : "memory");

        #pragma unroll
        for (int j = 0; j < LIF_BATCH; j++) {
            float2 xt;
            uint32_t src = slot0 + (uint32_t)rslot * stage_bytes;
            asm volatile("ld.shared.v2.f32 {%0,%1}, [%2];\n"
                         : "=f"(xt.x), "=f"(xt.y)
                         : "r"(src));
            if (++rslot == LIF_STAGES) rslot = 0;

            float2 sp;
            v.x = fmaf(LIF_TAU, v.x, xt.x);
            v.y = fmaf(LIF_TAU, v.y, xt.y);
            bool fx = v.x >= 1.0f, fy = v.y >= 1.0f;
            sp.x = fx ? 1.0f : 0.0f;  v.x = fx ? 0.0f : v.x;
            sp.y = fy ? 1.0f : 0.0f;  v.y = fy ? 0.0f : v.y;

            __stcs(op, sp);
            op += N2;
        }
    }
}

extern "C" void kernel_launch(void* const* d_in, const int* in_sizes, int n_in,
                              void* d_out, int out_size)
{
    const float* x  = (const float*)d_in[0];   // [T, B, D]
    const float* v0 = (const float*)d_in[1];   // [D]
    float* out = (float*)d_out;

    const int T = 512;                 // fixed by problem setup
    const int total = in_sizes[0];     // T*B*D
    const int D = in_sizes[1];
    const int N  = total / T;          // B*D
    const int N2 = N / 2;              // float2 chains
    const int D2 = D / 2;

    const int grid = (N2 + LIF_CTA - 1) / LIF_CTA;   // 128 for N2=32768
    lif_scan_kernel<<<grid, LIF_CTA>>>(x, v0, out, T, N2, D2);
}